// round 16
// baseline (speedup 1.0000x reference)
#include <cuda_runtime.h>
#include <cstdint>

// ---------------- compile-time shapes ----------------
static constexpr int B_ = 2;
static constexpr int D0 = 41, H0 = 512, W0 = 512;
static constexpr int D1 = 21, H1 = 256, W1 = 256;
static constexpr int D2 = 11, H2 = 128, W2 = 128;
static constexpr int D3 = 5,  H3 = 64,  W3 = 64;

static constexpr int N0 = B_ * D0 * H0 * W0;
static constexpr int N1 = B_ * D1 * H1 * W1;   // 2752512
static constexpr int N2 = B_ * D2 * H2 * W2;   // 360448
static constexpr int N3 = B_ * D3 * H3 * W3;   // 40960
static constexpr int N4 = B_ * 2 * H3 * W3;    // 16384
static constexpr int NW0 = N0 / 32;
static constexpr int NW1 = N1 / 32;             // 86016
static constexpr int CONV4_BLOCKS = (N4 * 32) / 256;   // 2048
static constexpr int CONV3_SMEM = (3 * 4096 + 3 * 2048) * 4;   // 73728 B

// ---------------- scratch ----------------
__device__ __align__(16) float4        g_dense0[N0];   // zero outside launch (invariant)
__device__ __align__(16) unsigned      g_bits[NW0];    // zero outside launch (invariant)
__device__ __align__(16) float         g_h1[(size_t)N1 * 16];
__device__ __align__(16) unsigned      g_m1bits[NW1];
__device__ __align__(16) float         g_h2[(size_t)N2 * 32];
__device__ unsigned char               g_m2[N2];
__device__ __align__(16) float         g_h3[(size_t)N3 * 64];
__device__ unsigned char               g_m3[N3];
__device__ __align__(16) uint2         g_wl[N1];       // worklist (idx, bits27)
__device__ unsigned                    g_wlcnt;

__device__ __align__(16) float g_wt1[27 * 3 * 16];      // [tap][ci][co]
__device__ __align__(16) float g_wt2[27 * 4 * 32 * 4];  // [tap][g4][co32][e4]
__device__ __align__(16) float g_wt3p[27 * 2048];       // [tap][c2][half][cog][q]
__device__ __align__(16) float g_wt4[3 * 16 * 64 * 4];  // [kd][g16][co64][e4]
__device__ float g_sc1[16], g_sh1[16];
__device__ float g_sc2[32], g_sh2[32];
__device__ float g_sc3[64], g_sh3[64];
__device__ float g_sc4[64], g_sh4[64];

// ---------------- packed f32x2 / cp.async helpers ----------------
__device__ __forceinline__ void ffma2(unsigned long long& acc,
                                      unsigned long long a, unsigned long long b) {
    asm("fma.rn.f32x2 %0, %1, %2, %0;" : "+l"(acc) : "l"(a), "l"(b));
}
__device__ __forceinline__ float hsum2(unsigned long long v) {
    float lo, hi;
    asm("mov.b64 {%0, %1}, %2;" : "=f"(lo), "=f"(hi) : "l"(v));
    return lo + hi;
}
__device__ __forceinline__ uint32_t smem_u32(const void* p) {
    uint32_t a;
    asm("{ .reg .u64 t; cvta.to.shared.u64 t, %1; cvt.u32.u64 %0, t; }" : "=r"(a) : "l"(p));
    return a;
}
#define CP_A16(dst, src, n) \
    asm volatile("cp.async.ca.shared.global [%0], [%1], 16, %2;" \
                 :: "r"(dst), "l"(src), "r"(n))
#define CP_COMMIT() asm volatile("cp.async.commit_group;" ::: "memory")
#define CP_WAIT1()  asm volatile("cp.async.wait_group 1;" ::: "memory")
#define CP_WAIT0()  asm volatile("cp.async.wait_group 0;" ::: "memory")

// ---------------- prep: weight transpose + BN fold ----------------
__global__ void k_prep(const float* __restrict__ w1, const float* __restrict__ g1,
                       const float* __restrict__ b1, const float* __restrict__ rm1,
                       const float* __restrict__ rv1,
                       const float* __restrict__ w2, const float* __restrict__ g2,
                       const float* __restrict__ b2, const float* __restrict__ rm2,
                       const float* __restrict__ rv2,
                       const float* __restrict__ w3, const float* __restrict__ g3,
                       const float* __restrict__ b3, const float* __restrict__ rm3,
                       const float* __restrict__ rv3,
                       const float* __restrict__ w4, const float* __restrict__ g4,
                       const float* __restrict__ b4, const float* __restrict__ rm4,
                       const float* __restrict__ rv4) {
    int i = blockIdx.x * blockDim.x + threadIdx.x;
    if (i < 1296) {
        int co = i & 15, ci = (i >> 4) % 3, tap = i / 48;
        g_wt1[i] = w1[(co * 3 + ci) * 27 + tap];
    }
    if (i < 13824) {
        int e = i & 3, co = (i >> 2) & 31, gg = (i >> 7) & 3, tap = i >> 9;
        g_wt2[i] = w2[(co * 16 + (4 * gg + e)) * 27 + tap];
    }
    if (i < 55296) {
        int tap = i >> 11;
        int rem = i & 2047;
        int c2 = rem >> 7;
        int rem2 = rem & 127;
        int half = rem2 >> 6;
        int rem3 = rem2 & 63;
        int cog = rem3 >> 2;
        int q = rem3 & 3;
        int co = cog * 4 + half * 2 + (q >> 1);
        int ci = c2 * 2 + (q & 1);
        g_wt3p[i] = w3[(co * 32 + ci) * 27 + tap];
    }
    if (i < 12288) {
        int e = i & 3, co = (i >> 2) & 63, gg = (i >> 8) & 15, kd = i >> 12;
        g_wt4[i] = w4[(co * 64 + (4 * gg + e)) * 3 + kd];
    }
    if (i < 16) { float s = g1[i] * rsqrtf(rv1[i] + 1e-3f); g_sc1[i] = s; g_sh1[i] = b1[i] - rm1[i] * s; }
    if (i < 32) { float s = g2[i] * rsqrtf(rv2[i] + 1e-3f); g_sc2[i] = s; g_sh2[i] = b2[i] - rm2[i] * s; }
    if (i < 64) {
        float s3 = g3[i] * rsqrtf(rv3[i] + 1e-3f); g_sc3[i] = s3; g_sh3[i] = b3[i] - rm3[i] * s3;
        float s4 = g4[i] * rsqrtf(rv4[i] + 1e-3f); g_sc4[i] = s4; g_sh4[i] = b4[i] - rm4[i] * s4;
    }
}

// ---------------- scatter (+ worklist counter reset) ----------------
__global__ void k_scat(const float* __restrict__ vf, const int* __restrict__ coors, int nv) {
    if (blockIdx.x == 0 && threadIdx.x == 0) g_wlcnt = 0;
    int i = blockIdx.x * blockDim.x + threadIdx.x;
    if (i >= nv) return;
    int b = coors[4*i], z = coors[4*i+1], y = coors[4*i+2], x = coors[4*i+3];
    size_t cell = (((size_t)b * D0 + z) * H0 + y) * W0 + x;
    float* p = reinterpret_cast<float*>(&g_dense0[cell]);
    atomicAdd(p + 0, vf[3*i + 0]);
    atomicAdd(p + 1, vf[3*i + 1]);
    atomicAdd(p + 2, vf[3*i + 2]);
    atomicOr(&g_bits[cell >> 5], 1u << (cell & 31));
}

// ---------------- mask1: build m1 bitmap + compact active worklist ----------------
__global__ void __launch_bounds__(128) k_mask1() {
    int idx = blockIdx.x * blockDim.x + threadIdx.x;
    int lane = threadIdx.x & 31;
    int ow = idx & 255; int t = idx >> 8;
    int oh = t & 255; t >>= 8;
    int od = t % D1; int b = t / D1;
    int base = ow - lane;
    int wk = base >> 4;

    unsigned bits27 = 0;
#pragma unroll
    for (int kd = 0; kd < 3; kd++) {
        int id = 2 * od - 1 + kd;
        bool dok = (unsigned)id < (unsigned)D0;
#pragma unroll
        for (int kh = 0; kh < 3; kh++) {
            int ih = 2 * oh - 1 + kh;
            bool rok = dok && ((unsigned)ih < (unsigned)H0);
            unsigned A = 0, Bw = 0, Cw = 0;
            if (rok) {
                size_t rw = ((((size_t)b * D0 + id) * H0) + ih) * (W0 / 32);
                if (wk > 0) A = g_bits[rw + wk - 1];
                Bw = g_bits[rw + wk];
                if (wk < 15) Cw = g_bits[rw + wk + 1];
            }
#pragma unroll
            for (int kw = 0; kw < 3; kw++) {
                unsigned qq = 2 * lane + 31 + kw;
                unsigned word = (qq < 32) ? A : ((qq < 64) ? Bw : Cw);
                unsigned bit = (word >> (qq & 31)) & 1u;
                bits27 |= bit << ((kd * 3 + kh) * 3 + kw);
            }
        }
    }
    unsigned act = __ballot_sync(0xffffffffu, bits27 != 0);
    if (lane == 0) g_m1bits[idx >> 5] = act;
    if (!act) return;

    unsigned baseIdx = 0;
    if (lane == 0) baseIdx = atomicAdd(&g_wlcnt, (unsigned)__popc(act));
    baseIdx = __shfl_sync(0xffffffffu, baseIdx, 0);
    if (bits27) {
        int rank = __popc(act & ((1u << lane) - 1u));
        g_wl[baseIdx + rank] = make_uint2((unsigned)idx, bits27);
    }
}

// ---------------- conv1b: compacted conv over active points ----------------
__global__ void __launch_bounds__(256) k_conv1b() {
    __shared__ __align__(16) float wsh[27 * 48];
    __shared__ float ssc[16], ssh[16];
    for (int i = threadIdx.x; i < 1296; i += 256) wsh[i] = g_wt1[i];
    if (threadIdx.x < 16) { ssc[threadIdx.x] = g_sc1[threadIdx.x]; ssh[threadIdx.x] = g_sh1[threadIdx.x]; }
    __syncthreads();

    unsigned cnt = g_wlcnt;
    for (unsigned i = blockIdx.x * 256 + threadIdx.x; i < cnt; i += gridDim.x * 256) {
        uint2 e = g_wl[i];
        int idx = (int)e.x;
        unsigned bits27 = e.y;
        int ow = idx & 255; int t = idx >> 8;
        int oh = t & 255; t >>= 8;
        int od = t % D1; int b = t / D1;

        float acc[16];
#pragma unroll
        for (int j = 0; j < 16; j++) acc[j] = 0.f;
        int base0 = ((b * D0 + (2 * od - 1)) * H0 + (2 * oh - 1)) * W0 + (2 * ow - 1);

        unsigned bits = bits27;
        while (bits) {
            int tap = __ffs(bits) - 1; bits &= bits - 1;
            int kd = tap / 9;
            int r9 = tap - 9 * kd;
            int kh = r9 / 3;
            int kw = r9 - 3 * kh;
            size_t cell = (size_t)(base0 + kd * (H0 * W0) + kh * W0 + kw);
            float4 v = __ldg(&g_dense0[cell]);
            float vv[3] = {v.x, v.y, v.z};
            const float4* wp = reinterpret_cast<const float4*>(&wsh[tap * 48]);
#pragma unroll
            for (int ci = 0; ci < 3; ci++) {
#pragma unroll
                for (int j = 0; j < 4; j++) {
                    float4 ww = wp[ci * 4 + j];
                    acc[j*4+0] = fmaf(vv[ci], ww.x, acc[j*4+0]);
                    acc[j*4+1] = fmaf(vv[ci], ww.y, acc[j*4+1]);
                    acc[j*4+2] = fmaf(vv[ci], ww.z, acc[j*4+2]);
                    acc[j*4+3] = fmaf(vv[ci], ww.w, acc[j*4+3]);
                }
            }
        }
        float* outp = &g_h1[(size_t)idx * 16];
#pragma unroll
        for (int j = 0; j < 4; j++) {
            float4 o;
            o.x = fmaxf(fmaf(acc[j*4+0], ssc[j*4+0], ssh[j*4+0]), 0.f);
            o.y = fmaxf(fmaf(acc[j*4+1], ssc[j*4+1], ssh[j*4+1]), 0.f);
            o.z = fmaxf(fmaf(acc[j*4+2], ssc[j*4+2], ssh[j*4+2]), 0.f);
            o.w = fmaxf(fmaf(acc[j*4+3], ssc[j*4+3], ssh[j*4+3]), 0.f);
            reinterpret_cast<float4*>(outp)[j] = o;
        }
    }
}

// ---------------- conv2 (R7 v3): tap-major, 32 points/warp ----------------
__global__ void __launch_bounds__(256) k_conv2() {
    __shared__ float accS[256 * 33];

    int tid = threadIdx.x;
    int lane = tid & 31;
    int pidx = blockIdx.x * 256 + tid;
    int ow = pidx & 127;
    int oh = (pidx >> 7) & 127;
    int tq = pidx >> 14;
    int od = tq % D2;
    int b = tq / D2;
    int ow0 = ow - lane;
    int wbase = tid - lane;

#pragma unroll 8
    for (int p = 0; p < 32; p++) accS[(wbase + p) * 33 + lane] = 0.f;

    unsigned mask = 0;
    int k0 = (2 * ow0) >> 5;
#pragma unroll
    for (int r = 0; r < 9; r++) {
        const int kd = r / 3, kh = r % 3;
        int id = 2 * od - 1 + kd;
        int ih = 2 * oh - 1 + kh;
        unsigned w1v = 0, w2v = 0, wpv = 0;
        if ((unsigned)id < (unsigned)D1 && (unsigned)ih < (unsigned)H1) {
            size_t rw = (((size_t)b * D1 + id) * H1 + ih) * (W1 / 32);
            w1v = g_m1bits[rw + k0];
            w2v = g_m1bits[rw + k0 + 1];
            if (k0 > 0) wpv = g_m1bits[rw + k0 - 1];
        }
        unsigned long long win = (unsigned long long)(wpv >> 31)
                               | ((unsigned long long)w1v << 1)
                               | ((unsigned long long)w2v << 33);
        unsigned tri = (unsigned)((win >> (2 * lane)) & 7ull);
        if (lane == 31) tri = (tri & 3u) | (((w2v >> 31) & 1u) << 2);
        mask |= tri << (r * 3);
    }

    unsigned warpU = __reduce_or_sync(0xffffffffu, mask);

    if (warpU) {
        const ulonglong2* wtb = reinterpret_cast<const ulonglong2*>(g_wt2);
        int C0 = ((b * D1 + (2 * od - 1)) * H1 + (2 * oh - 1)) * W1 + (2 * ow0 - 1);
        unsigned bits = warpU;
        while (bits) {
            int tap = __ffs(bits) - 1; bits &= bits - 1;
            int kd = tap / 9;
            int r9 = tap - kd * 9;
            int kh = r9 / 3;
            int kw = r9 - kh * 3;
            const ulonglong2* wv = wtb + tap * 128 + lane;
            ulonglong2 ww0 = __ldg(wv);
            ulonglong2 ww1 = __ldg(wv + 32);
            ulonglong2 ww2 = __ldg(wv + 64);
            ulonglong2 ww3 = __ldg(wv + 96);
            unsigned actp = __ballot_sync(0xffffffffu, (mask >> tap) & 1u);
            int cin0 = C0 + kd * (H1 * W1) + kh * W1 + kw;
            while (actp) {
                int p = __ffs(actp) - 1; actp &= actp - 1;
                const ulonglong2* h =
                    reinterpret_cast<const ulonglong2*>(&g_h1[(size_t)(cin0 + 2 * p) * 16]);
                ulonglong2 v0 = __ldg(h);
                ulonglong2 v1 = __ldg(h + 1);
                ulonglong2 v2 = __ldg(h + 2);
                ulonglong2 v3 = __ldg(h + 3);
                unsigned long long s0 = 0ull, s1 = 0ull;
                ffma2(s0, v0.x, ww0.x); ffma2(s1, v0.y, ww0.y);
                ffma2(s0, v1.x, ww1.x); ffma2(s1, v1.y, ww1.y);
                ffma2(s0, v2.x, ww2.x); ffma2(s1, v2.y, ww2.y);
                ffma2(s0, v3.x, ww3.x); ffma2(s1, v3.y, ww3.y);
                accS[(wbase + p) * 33 + lane] += hsum2(s0) + hsum2(s1);
            }
        }
    }

    int pbase = pidx - lane;
    float sc = g_sc2[lane], shv = g_sh2[lane];
#pragma unroll 4
    for (int p = 0; p < 32; p++) {
        float a = accS[(wbase + p) * 33 + lane];
        unsigned mp = __shfl_sync(0xffffffffu, mask, p);
        float m = mp ? 1.f : 0.f;
        g_h2[(size_t)(pbase + p) * 32 + lane] = fmaxf(fmaf(a, sc, shv), 0.f) * m;
    }
    g_m2[pbase + lane] = (mask != 0) ? 1 : 0;
}

// ---------------- conv3: 128-pt tile (8oh x 16ow), 512 thr, 3-stage cp.async, f32x2 ----------------
// dynamic smem: As[3][4096] then Ws[3][2048]  (73728 B)
__global__ void __launch_bounds__(512) k_conv3() {
    extern __shared__ __align__(16) float dynS[];
    float* As  = dynS;             // 3 x 4096
    float* Wst = dynS + 3 * 4096;  // 3 x 2048
    __shared__ float mS[128];

    int bx = blockIdx.x;                 // 320 blocks
    int ow0 = (bx & 3) * 16;
    int oh0 = ((bx >> 2) & 7) * 8;
    int odb = bx >> 5;                   // 0..9
    int od = odb % D3, b = odb / D3;

    int tid = threadIdx.x;
    int cog = tid & 15;  int co4 = cog * 4;
    int p4 = (tid >> 4) * 4;             // 0..124

    unsigned long long acc2[16];
#pragma unroll
    for (int i = 0; i < 16; i++) acc2[i] = 0ull;

    const float4* h2f4  = reinterpret_cast<const float4*>(g_h2);
    const float4* wt3p4 = reinterpret_cast<const float4*>(g_wt3p);
    uint32_t asAddr = smem_u32(As);
    uint32_t wsAddr = smem_u32(Wst);

    // staging geometry: thread stages A elements tid and tid+512, W element tid
    int pA0 = tid >> 3,         fA = tid & 7;
    int pA1 = (tid + 512) >> 3;
    int diA0 = pA0 >> 4, djA0 = pA0 & 15;
    int diA1 = pA1 >> 4, djA1 = pA1 & 15;

    auto stage = [&](int slot, int tap) {
        int kd = tap / 9; int r9 = tap - 9 * kd; int kh = r9 / 3; int kw = r9 - 3 * kh;
        int id = 2 * od + kd;
        size_t plane = (((size_t)b * D2 + id) * H2) * W2;
        {
            int ih = 2 * (oh0 + diA0) - 1 + kh, iw = 2 * (ow0 + djA0) - 1 + kw;
            bool ok = ((unsigned)ih < (unsigned)H2) && ((unsigned)iw < (unsigned)W2);
            const float4* src = ok ? &h2f4[(plane + (size_t)ih * W2 + iw) * 8 + fA] : h2f4;
            CP_A16(asAddr + (unsigned)(slot * 1024 + tid) * 16, src, ok ? 16 : 0);
        }
        {
            int ih = 2 * (oh0 + diA1) - 1 + kh, iw = 2 * (ow0 + djA1) - 1 + kw;
            bool ok = ((unsigned)ih < (unsigned)H2) && ((unsigned)iw < (unsigned)W2);
            const float4* src = ok ? &h2f4[(plane + (size_t)ih * W2 + iw) * 8 + fA] : h2f4;
            CP_A16(asAddr + (unsigned)(slot * 1024 + tid + 512) * 16, src, ok ? 16 : 0);
        }
        CP_A16(wsAddr + (unsigned)(slot * 512 + tid) * 16, &wt3p4[tap * 512 + tid], 16);
        CP_COMMIT();
    };

    // fused m3: threads 0..127 compute 27-neighbor OR for their point
    if (tid < 128) {
        int di = tid >> 4, dj = tid & 15;
        int ohp = oh0 + di, owp = ow0 + dj;
        unsigned char m = 0;
#pragma unroll
        for (int kd = 0; kd < 3; kd++) {
            int id = 2 * od + kd;
#pragma unroll
            for (int kh = 0; kh < 3; kh++) {
                int ih = 2 * ohp - 1 + kh;
                if ((unsigned)ih >= (unsigned)H2) continue;
#pragma unroll
                for (int kw = 0; kw < 3; kw++) {
                    int iw = 2 * owp - 1 + kw;
                    if ((unsigned)iw >= (unsigned)W2) continue;
                    size_t cin = (((size_t)b * D2 + id) * H2 + ih) * W2 + iw;
                    m |= g_m2[cin];
                }
            }
        }
        unsigned char mv = m ? 1 : 0;
        mS[tid] = (float)mv;
        g_m3[((b * D3 + od) * H3 + ohp) * W3 + owp] = mv;
    }

    stage(0, 0);
    stage(1, 1);

    int slotc = 0;
#pragma unroll 1
    for (int tap = 0; tap < 27; tap++) {
        if (tap < 26) CP_WAIT1(); else CP_WAIT0();
        __syncthreads();                     // single barrier per tap

        const float* Asb = As + slotc * 4096;
        const float* Wsb = Wst + slotc * 2048;
#pragma unroll
        for (int c4 = 0; c4 < 8; c4++) {
            ulonglong2 wa01 = *reinterpret_cast<const ulonglong2*>(&Wsb[(2*c4) * 128 + cog * 4]);
            ulonglong2 wa23 = *reinterpret_cast<const ulonglong2*>(&Wsb[(2*c4) * 128 + 64 + cog * 4]);
            ulonglong2 wb01 = *reinterpret_cast<const ulonglong2*>(&Wsb[(2*c4+1) * 128 + cog * 4]);
            ulonglong2 wb23 = *reinterpret_cast<const ulonglong2*>(&Wsb[(2*c4+1) * 128 + 64 + cog * 4]);
            ulonglong2 A0 = *reinterpret_cast<const ulonglong2*>(&Asb[(p4 + 0) * 32 + 4 * c4]);
            ulonglong2 A1 = *reinterpret_cast<const ulonglong2*>(&Asb[(p4 + 1) * 32 + 4 * c4]);
            ulonglong2 A2 = *reinterpret_cast<const ulonglong2*>(&Asb[(p4 + 2) * 32 + 4 * c4]);
            ulonglong2 A3 = *reinterpret_cast<const ulonglong2*>(&Asb[(p4 + 3) * 32 + 4 * c4]);
            ffma2(acc2[0],  A0.x, wa01.x); ffma2(acc2[1],  A0.x, wa01.y);
            ffma2(acc2[2],  A0.x, wa23.x); ffma2(acc2[3],  A0.x, wa23.y);
            ffma2(acc2[0],  A0.y, wb01.x); ffma2(acc2[1],  A0.y, wb01.y);
            ffma2(acc2[2],  A0.y, wb23.x); ffma2(acc2[3],  A0.y, wb23.y);
            ffma2(acc2[4],  A1.x, wa01.x); ffma2(acc2[5],  A1.x, wa01.y);
            ffma2(acc2[6],  A1.x, wa23.x); ffma2(acc2[7],  A1.x, wa23.y);
            ffma2(acc2[4],  A1.y, wb01.x); ffma2(acc2[5],  A1.y, wb01.y);
            ffma2(acc2[6],  A1.y, wb23.x); ffma2(acc2[7],  A1.y, wb23.y);
            ffma2(acc2[8],  A2.x, wa01.x); ffma2(acc2[9],  A2.x, wa01.y);
            ffma2(acc2[10], A2.x, wa23.x); ffma2(acc2[11], A2.x, wa23.y);
            ffma2(acc2[8],  A2.y, wb01.x); ffma2(acc2[9],  A2.y, wb01.y);
            ffma2(acc2[10], A2.y, wb23.x); ffma2(acc2[11], A2.y, wb23.y);
            ffma2(acc2[12], A3.x, wa01.x); ffma2(acc2[13], A3.x, wa01.y);
            ffma2(acc2[14], A3.x, wa23.x); ffma2(acc2[15], A3.x, wa23.y);
            ffma2(acc2[12], A3.y, wb01.x); ffma2(acc2[13], A3.y, wb01.y);
            ffma2(acc2[14], A3.y, wb23.x); ffma2(acc2[15], A3.y, wb23.y);
        }

        if (tap + 2 < 27) {
            int slotn = slotc + 2; if (slotn >= 3) slotn -= 3;
            stage(slotn, tap + 2);           // writes slot != current, != next
        }
        if (++slotc == 3) slotc = 0;
    }

    float sc[4], sh[4];
#pragma unroll
    for (int j = 0; j < 4; j++) { sc[j] = g_sc3[co4 + j]; sh[j] = g_sh3[co4 + j]; }
#pragma unroll
    for (int e = 0; e < 4; e++) {
        int p = p4 + e;
        int di = p >> 4, dj = p & 15;
        int lin = ((b * D3 + od) * H3 + (oh0 + di)) * W3 + (ow0 + dj);
        float m = mS[p];
        float4 o;
        o.x = fmaxf(fmaf(hsum2(acc2[e*4+0]), sc[0], sh[0]), 0.f) * m;
        o.y = fmaxf(fmaf(hsum2(acc2[e*4+1]), sc[1], sh[1]), 0.f) * m;
        o.z = fmaxf(fmaf(hsum2(acc2[e*4+2]), sc[2], sh[2]), 0.f) * m;
        o.w = fmaxf(fmaf(hsum2(acc2[e*4+3]), sc[3], sh[3]), 0.f) * m;
        *reinterpret_cast<float4*>(&g_h3[(size_t)lin * 64 + co4]) = o;
    }
}

// ---------------- conv4 + fused clean ----------------
__global__ void __launch_bounds__(256) k_conv4(float* __restrict__ out,
                                               const int* __restrict__ coors, int nv) {
    if (blockIdx.x >= CONV4_BLOCKS) {
        int i = (blockIdx.x - CONV4_BLOCKS) * 256 + threadIdx.x;
        if (i < nv) {
            int b = coors[4*i], z = coors[4*i+1], y = coors[4*i+2], x = coors[4*i+3];
            size_t cell = (((size_t)b * D0 + z) * H0 + y) * W0 + x;
            g_dense0[cell] = make_float4(0.f, 0.f, 0.f, 0.f);
            g_bits[cell >> 5] = 0u;
        }
        return;
    }

    int gw = (blockIdx.x * blockDim.x + threadIdx.x) >> 5;
    int lane = threadIdx.x & 31;
    int ow = gw & 63; int t = gw >> 6;
    int oh = t & 63; t >>= 6;
    int od = t & 1; int b = t >> 1;

    unsigned on = 0;
    if (lane < 3) {
        int id = 2*od + lane;
        size_t cin = (((size_t)b * D3 + id) * H3 + oh) * W3 + ow;
        on = g_m3[cin];
    }
    unsigned bits = __ballot_sync(0xffffffffu, on != 0);

    size_t obase = (size_t)b * 128 * 4096 + (size_t)oh * 64 + ow;
    size_t oi0 = obase + (size_t)(lane * 2 + od) * 4096;
    size_t oi1 = obase + (size_t)((lane + 32) * 2 + od) * 4096;

    if (!bits) { out[oi0] = 0.f; out[oi1] = 0.f; return; }

    unsigned long long acc0 = 0ull, acc1 = 0ull;
    const ulonglong2* wtb = reinterpret_cast<const ulonglong2*>(g_wt4);
#pragma unroll
    for (int kd = 0; kd < 3; kd++) {
        if (bits & (1u << kd)) {
            int id = 2*od + kd;
            size_t cin = (((size_t)b * D3 + id) * H3 + oh) * W3 + ow;
            const ulonglong2* hin = reinterpret_cast<const ulonglong2*>(&g_h3[cin * 64]);
            const ulonglong2* wv = wtb + kd * 1024 + lane;
#pragma unroll
            for (int gg = 0; gg < 16; gg++) {
                ulonglong2 v  = __ldg(hin + gg);
                ulonglong2 w0 = __ldg(wv + gg * 64);
                ulonglong2 w1 = __ldg(wv + gg * 64 + 32);
                ffma2(acc0, v.x, w0.x); ffma2(acc0, v.y, w0.y);
                ffma2(acc1, v.x, w1.x); ffma2(acc1, v.y, w1.y);
            }
        }
    }
    out[oi0] = fmaxf(fmaf(hsum2(acc0), g_sc4[lane],      g_sh4[lane]),      0.f);
    out[oi1] = fmaxf(fmaf(hsum2(acc1), g_sc4[lane + 32], g_sh4[lane + 32]), 0.f);
}

// ---------------- launch ----------------
extern "C" void kernel_launch(void* const* d_in, const int* in_sizes, int n_in,
                              void* d_out, int out_size) {
    const float* vf    = (const float*)d_in[0];
    const int*   coors = (const int*)d_in[1];
    int nv = in_sizes[0] / 3;

    const float* w1 = (const float*)d_in[3];  const float* g1 = (const float*)d_in[4];
    const float* b1 = (const float*)d_in[5];  const float* m1 = (const float*)d_in[6];
    const float* v1 = (const float*)d_in[7];
    const float* w2 = (const float*)d_in[8];  const float* g2 = (const float*)d_in[9];
    const float* b2 = (const float*)d_in[10]; const float* m2 = (const float*)d_in[11];
    const float* v2 = (const float*)d_in[12];
    const float* w3 = (const float*)d_in[13]; const float* g3 = (const float*)d_in[14];
    const float* b3 = (const float*)d_in[15]; const float* m3 = (const float*)d_in[16];
    const float* v3 = (const float*)d_in[17];
    const float* w4 = (const float*)d_in[18]; const float* g4 = (const float*)d_in[19];
    const float* b4 = (const float*)d_in[20]; const float* m4 = (const float*)d_in[21];
    const float* v4 = (const float*)d_in[22];

    cudaFuncSetAttribute(k_conv3, cudaFuncAttributeMaxDynamicSharedMemorySize, CONV3_SMEM);

    int scat_blocks = (nv + 255) / 256;
    k_prep<<<216, 256>>>(w1, g1, b1, m1, v1,
                         w2, g2, b2, m2, v2,
                         w3, g3, b3, m3, v3,
                         w4, g4, b4, m4, v4);
    k_scat<<<scat_blocks, 256>>>(vf, coors, nv);
    k_mask1<<<N1 / 128, 128>>>();
    k_conv1b<<<2048, 256>>>();
    k_conv2<<<N2 / 256, 256>>>();
    k_conv3<<<320, 512, CONV3_SMEM>>>();
    k_conv4<<<CONV4_BLOCKS + scat_blocks, 256>>>((float*)d_out, coors, nv);
}

// round 17
// speedup vs baseline: 1.1947x; 1.1947x over previous
#include <cuda_runtime.h>
#include <cstdint>

// ---------------- compile-time shapes ----------------
static constexpr int B_ = 2;
static constexpr int D0 = 41, H0 = 512, W0 = 512;
static constexpr int D1 = 21, H1 = 256, W1 = 256;
static constexpr int D2 = 11, H2 = 128, W2 = 128;
static constexpr int D3 = 5,  H3 = 64,  W3 = 64;

static constexpr int N0 = B_ * D0 * H0 * W0;
static constexpr int N1 = B_ * D1 * H1 * W1;   // 2752512
static constexpr int N2 = B_ * D2 * H2 * W2;   // 360448
static constexpr int N3 = B_ * D3 * H3 * W3;   // 40960
static constexpr int N4 = B_ * 2 * H3 * W3;    // 16384
static constexpr int NW0 = N0 / 32;
static constexpr int NW1 = N1 / 32;             // 86016
static constexpr int CONV4_BLOCKS = (N4 * 32) / 256;   // 2048
static constexpr int CONV3_SMEM = 3 * 2048 * 2 * 4;    // 49152 B

// ---------------- scratch ----------------
__device__ __align__(16) float4        g_dense0[N0];   // zero outside launch (invariant)
__device__ __align__(16) unsigned      g_bits[NW0];    // zero outside launch (invariant)
__device__ __align__(16) float         g_h1[(size_t)N1 * 16];
__device__ __align__(16) unsigned      g_m1bits[NW1];
__device__ __align__(16) float         g_h2[(size_t)N2 * 32];
__device__ unsigned char               g_m2[N2];
__device__ __align__(16) float         g_h3[(size_t)N3 * 64];
__device__ unsigned char               g_m3[N3];
__device__ __align__(16) uint2         g_wl[N1];       // worklist (idx, bits27)
__device__ unsigned                    g_wlcnt;

__device__ __align__(16) float g_wt1[27 * 3 * 16];      // [tap][ci][co]
__device__ __align__(16) float g_wt2[27 * 4 * 32 * 4];  // [tap][g4][co32][e4]
__device__ __align__(16) float g_wt3p[27 * 2048];       // [tap][c2][half][cog][q]
__device__ __align__(16) float g_wt4[3 * 16 * 64 * 4];  // [kd][g16][co64][e4]
__device__ float g_sc1[16], g_sh1[16];
__device__ float g_sc2[32], g_sh2[32];
__device__ float g_sc3[64], g_sh3[64];
__device__ float g_sc4[64], g_sh4[64];

// ---------------- packed f32x2 / cp.async helpers ----------------
__device__ __forceinline__ void ffma2(unsigned long long& acc,
                                      unsigned long long a, unsigned long long b) {
    asm("fma.rn.f32x2 %0, %1, %2, %0;" : "+l"(acc) : "l"(a), "l"(b));
}
__device__ __forceinline__ float hsum2(unsigned long long v) {
    float lo, hi;
    asm("mov.b64 {%0, %1}, %2;" : "=f"(lo), "=f"(hi) : "l"(v));
    return lo + hi;
}
__device__ __forceinline__ uint32_t smem_u32(const void* p) {
    uint32_t a;
    asm("{ .reg .u64 t; cvta.to.shared.u64 t, %1; cvt.u32.u64 %0, t; }" : "=r"(a) : "l"(p));
    return a;
}
#define CP_A16(dst, src, n) \
    asm volatile("cp.async.ca.shared.global [%0], [%1], 16, %2;" \
                 :: "r"(dst), "l"(src), "r"(n))
#define CP_COMMIT() asm volatile("cp.async.commit_group;" ::: "memory")
#define CP_WAIT1()  asm volatile("cp.async.wait_group 1;" ::: "memory")
#define CP_WAIT0()  asm volatile("cp.async.wait_group 0;" ::: "memory")

// ---------------- prep: weight transpose + BN fold ----------------
__global__ void k_prep(const float* __restrict__ w1, const float* __restrict__ g1,
                       const float* __restrict__ b1, const float* __restrict__ rm1,
                       const float* __restrict__ rv1,
                       const float* __restrict__ w2, const float* __restrict__ g2,
                       const float* __restrict__ b2, const float* __restrict__ rm2,
                       const float* __restrict__ rv2,
                       const float* __restrict__ w3, const float* __restrict__ g3,
                       const float* __restrict__ b3, const float* __restrict__ rm3,
                       const float* __restrict__ rv3,
                       const float* __restrict__ w4, const float* __restrict__ g4,
                       const float* __restrict__ b4, const float* __restrict__ rm4,
                       const float* __restrict__ rv4) {
    int i = blockIdx.x * blockDim.x + threadIdx.x;
    if (i < 1296) {
        int co = i & 15, ci = (i >> 4) % 3, tap = i / 48;
        g_wt1[i] = w1[(co * 3 + ci) * 27 + tap];
    }
    if (i < 13824) {
        int e = i & 3, co = (i >> 2) & 31, gg = (i >> 7) & 3, tap = i >> 9;
        g_wt2[i] = w2[(co * 16 + (4 * gg + e)) * 27 + tap];
    }
    if (i < 55296) {
        int tap = i >> 11;
        int rem = i & 2047;
        int c2 = rem >> 7;
        int rem2 = rem & 127;
        int half = rem2 >> 6;
        int rem3 = rem2 & 63;
        int cog = rem3 >> 2;
        int q = rem3 & 3;
        int co = cog * 4 + half * 2 + (q >> 1);
        int ci = c2 * 2 + (q & 1);
        g_wt3p[i] = w3[(co * 32 + ci) * 27 + tap];
    }
    if (i < 12288) {
        int e = i & 3, co = (i >> 2) & 63, gg = (i >> 8) & 15, kd = i >> 12;
        g_wt4[i] = w4[(co * 64 + (4 * gg + e)) * 3 + kd];
    }
    if (i < 16) { float s = g1[i] * rsqrtf(rv1[i] + 1e-3f); g_sc1[i] = s; g_sh1[i] = b1[i] - rm1[i] * s; }
    if (i < 32) { float s = g2[i] * rsqrtf(rv2[i] + 1e-3f); g_sc2[i] = s; g_sh2[i] = b2[i] - rm2[i] * s; }
    if (i < 64) {
        float s3 = g3[i] * rsqrtf(rv3[i] + 1e-3f); g_sc3[i] = s3; g_sh3[i] = b3[i] - rm3[i] * s3;
        float s4 = g4[i] * rsqrtf(rv4[i] + 1e-3f); g_sc4[i] = s4; g_sh4[i] = b4[i] - rm4[i] * s4;
    }
}

// ---------------- scatter (+ worklist counter reset) ----------------
__global__ void k_scat(const float* __restrict__ vf, const int* __restrict__ coors, int nv) {
    if (blockIdx.x == 0 && threadIdx.x == 0) g_wlcnt = 0;
    int i = blockIdx.x * blockDim.x + threadIdx.x;
    if (i >= nv) return;
    int b = coors[4*i], z = coors[4*i+1], y = coors[4*i+2], x = coors[4*i+3];
    size_t cell = (((size_t)b * D0 + z) * H0 + y) * W0 + x;
    float* p = reinterpret_cast<float*>(&g_dense0[cell]);
    atomicAdd(p + 0, vf[3*i + 0]);
    atomicAdd(p + 1, vf[3*i + 1]);
    atomicAdd(p + 2, vf[3*i + 2]);
    atomicOr(&g_bits[cell >> 5], 1u << (cell & 31));
}

// ---------------- mask1 v2: 64 points/warp, bitmap -> masks + compacted worklist ----------------
__global__ void __launch_bounds__(128) k_mask1() {
    int lane = threadIdx.x & 31;
    int wid = threadIdx.x >> 5;
    int pbase = blockIdx.x * 256 + wid * 64;     // 64-aligned point run
    int ow0 = pbase & 255;                        // {0,64,128,192}
    int t = pbase >> 8;
    int oh = t & 255; t >>= 8;
    int od = t % D1; int b = t / D1;
    int k0 = (2 * ow0) >> 5;                      // {0,4,8,12}; words k0..k0+3 valid (<=15)

    unsigned maskA = 0, maskB = 0;                // points pbase+lane, pbase+32+lane
#pragma unroll
    for (int r = 0; r < 9; r++) {
        int kd = r / 3, kh = r % 3;
        int id = 2 * od - 1 + kd;
        int ih = 2 * oh - 1 + kh;
        if ((unsigned)id >= (unsigned)D0 || (unsigned)ih >= (unsigned)H0) continue;
        size_t rw = (((size_t)b * D0 + id) * H0 + ih) * (W0 / 32);
        unsigned wp = (k0 > 0) ? g_bits[rw + k0 - 1] : 0u;
        unsigned w0 = g_bits[rw + k0 + 0];
        unsigned w1 = g_bits[rw + k0 + 1];
        unsigned w2 = g_bits[rw + k0 + 2];
        unsigned w3 = g_bits[rw + k0 + 3];
        // column j <-> iw = 2*ow0 - 1 + j, j in [0,128]; point p uses bits 2p..2p+2
        unsigned long long cm0 = (unsigned long long)(wp >> 31)
                               | ((unsigned long long)w0 << 1)
                               | ((unsigned long long)w1 << 33);    // j = 0..63
        unsigned long long cm1 = (unsigned long long)(w1 >> 31)
                               | ((unsigned long long)w2 << 1)
                               | ((unsigned long long)w3 << 33);    // j = 64..127
        unsigned tail = w3 >> 31;                                   // j = 128
        unsigned triA = (lane < 31)
            ? (unsigned)((cm0 >> (2 * lane)) & 7ull)
            : (unsigned)(((cm0 >> 62) & 3ull) | (((unsigned)cm1 & 1u) << 2));
        unsigned triB = (lane < 31)
            ? (unsigned)((cm1 >> (2 * lane)) & 7ull)
            : (unsigned)(((cm1 >> 62) & 3ull) | (tail << 2));
        maskA |= triA << (r * 3);
        maskB |= triB << (r * 3);
    }

    unsigned actA = __ballot_sync(0xffffffffu, maskA != 0);
    unsigned actB = __ballot_sync(0xffffffffu, maskB != 0);
    if (lane == 0) {
        g_m1bits[(pbase >> 5) + 0] = actA;
        g_m1bits[(pbase >> 5) + 1] = actB;
    }
    if (!(actA | actB)) return;

    unsigned cntw = (unsigned)(__popc(actA) + __popc(actB));
    unsigned baseIdx = 0;
    if (lane == 0) baseIdx = atomicAdd(&g_wlcnt, cntw);
    baseIdx = __shfl_sync(0xffffffffu, baseIdx, 0);
    if (maskA) {
        int rank = __popc(actA & ((1u << lane) - 1u));
        g_wl[baseIdx + rank] = make_uint2((unsigned)(pbase + lane), maskA);
    }
    if (maskB) {
        int rank = __popc(actA) + __popc(actB & ((1u << lane) - 1u));
        g_wl[baseIdx + rank] = make_uint2((unsigned)(pbase + 32 + lane), maskB);
    }
}

// ---------------- conv1b: compacted conv over active points ----------------
__global__ void __launch_bounds__(256) k_conv1b() {
    __shared__ __align__(16) float wsh[27 * 48];
    __shared__ float ssc[16], ssh[16];
    for (int i = threadIdx.x; i < 1296; i += 256) wsh[i] = g_wt1[i];
    if (threadIdx.x < 16) { ssc[threadIdx.x] = g_sc1[threadIdx.x]; ssh[threadIdx.x] = g_sh1[threadIdx.x]; }
    __syncthreads();

    unsigned cnt = g_wlcnt;
    for (unsigned i = blockIdx.x * 256 + threadIdx.x; i < cnt; i += gridDim.x * 256) {
        uint2 e = g_wl[i];
        int idx = (int)e.x;
        unsigned bits27 = e.y;
        int ow = idx & 255; int t = idx >> 8;
        int oh = t & 255; t >>= 8;
        int od = t % D1; int b = t / D1;

        float acc[16];
#pragma unroll
        for (int j = 0; j < 16; j++) acc[j] = 0.f;
        int base0 = ((b * D0 + (2 * od - 1)) * H0 + (2 * oh - 1)) * W0 + (2 * ow - 1);

        unsigned bits = bits27;
        while (bits) {
            int tap = __ffs(bits) - 1; bits &= bits - 1;
            int kd = tap / 9;
            int r9 = tap - 9 * kd;
            int kh = r9 / 3;
            int kw = r9 - 3 * kh;
            size_t cell = (size_t)(base0 + kd * (H0 * W0) + kh * W0 + kw);
            float4 v = __ldg(&g_dense0[cell]);
            float vv[3] = {v.x, v.y, v.z};
            const float4* wp = reinterpret_cast<const float4*>(&wsh[tap * 48]);
#pragma unroll
            for (int ci = 0; ci < 3; ci++) {
#pragma unroll
                for (int j = 0; j < 4; j++) {
                    float4 ww = wp[ci * 4 + j];
                    acc[j*4+0] = fmaf(vv[ci], ww.x, acc[j*4+0]);
                    acc[j*4+1] = fmaf(vv[ci], ww.y, acc[j*4+1]);
                    acc[j*4+2] = fmaf(vv[ci], ww.z, acc[j*4+2]);
                    acc[j*4+3] = fmaf(vv[ci], ww.w, acc[j*4+3]);
                }
            }
        }
        float* outp = &g_h1[(size_t)idx * 16];
#pragma unroll
        for (int j = 0; j < 4; j++) {
            float4 o;
            o.x = fmaxf(fmaf(acc[j*4+0], ssc[j*4+0], ssh[j*4+0]), 0.f);
            o.y = fmaxf(fmaf(acc[j*4+1], ssc[j*4+1], ssh[j*4+1]), 0.f);
            o.z = fmaxf(fmaf(acc[j*4+2], ssc[j*4+2], ssh[j*4+2]), 0.f);
            o.w = fmaxf(fmaf(acc[j*4+3], ssc[j*4+3], ssh[j*4+3]), 0.f);
            reinterpret_cast<float4*>(outp)[j] = o;
        }
    }
}

// ---------------- conv2 (R7 v3): tap-major, 32 points/warp ----------------
__global__ void __launch_bounds__(256) k_conv2() {
    __shared__ float accS[256 * 33];

    int tid = threadIdx.x;
    int lane = tid & 31;
    int pidx = blockIdx.x * 256 + tid;
    int ow = pidx & 127;
    int oh = (pidx >> 7) & 127;
    int tq = pidx >> 14;
    int od = tq % D2;
    int b = tq / D2;
    int ow0 = ow - lane;
    int wbase = tid - lane;

#pragma unroll 8
    for (int p = 0; p < 32; p++) accS[(wbase + p) * 33 + lane] = 0.f;

    unsigned mask = 0;
    int k0 = (2 * ow0) >> 5;
#pragma unroll
    for (int r = 0; r < 9; r++) {
        const int kd = r / 3, kh = r % 3;
        int id = 2 * od - 1 + kd;
        int ih = 2 * oh - 1 + kh;
        unsigned w1v = 0, w2v = 0, wpv = 0;
        if ((unsigned)id < (unsigned)D1 && (unsigned)ih < (unsigned)H1) {
            size_t rw = (((size_t)b * D1 + id) * H1 + ih) * (W1 / 32);
            w1v = g_m1bits[rw + k0];
            w2v = g_m1bits[rw + k0 + 1];
            if (k0 > 0) wpv = g_m1bits[rw + k0 - 1];
        }
        unsigned long long win = (unsigned long long)(wpv >> 31)
                               | ((unsigned long long)w1v << 1)
                               | ((unsigned long long)w2v << 33);
        unsigned tri = (unsigned)((win >> (2 * lane)) & 7ull);
        if (lane == 31) tri = (tri & 3u) | (((w2v >> 31) & 1u) << 2);
        mask |= tri << (r * 3);
    }

    unsigned warpU = __reduce_or_sync(0xffffffffu, mask);

    if (warpU) {
        const ulonglong2* wtb = reinterpret_cast<const ulonglong2*>(g_wt2);
        int C0 = ((b * D1 + (2 * od - 1)) * H1 + (2 * oh - 1)) * W1 + (2 * ow0 - 1);
        unsigned bits = warpU;
        while (bits) {
            int tap = __ffs(bits) - 1; bits &= bits - 1;
            int kd = tap / 9;
            int r9 = tap - kd * 9;
            int kh = r9 / 3;
            int kw = r9 - kh * 3;
            const ulonglong2* wv = wtb + tap * 128 + lane;
            ulonglong2 ww0 = __ldg(wv);
            ulonglong2 ww1 = __ldg(wv + 32);
            ulonglong2 ww2 = __ldg(wv + 64);
            ulonglong2 ww3 = __ldg(wv + 96);
            unsigned actp = __ballot_sync(0xffffffffu, (mask >> tap) & 1u);
            int cin0 = C0 + kd * (H1 * W1) + kh * W1 + kw;
            while (actp) {
                int p = __ffs(actp) - 1; actp &= actp - 1;
                const ulonglong2* h =
                    reinterpret_cast<const ulonglong2*>(&g_h1[(size_t)(cin0 + 2 * p) * 16]);
                ulonglong2 v0 = __ldg(h);
                ulonglong2 v1 = __ldg(h + 1);
                ulonglong2 v2 = __ldg(h + 2);
                ulonglong2 v3 = __ldg(h + 3);
                unsigned long long s0 = 0ull, s1 = 0ull;
                ffma2(s0, v0.x, ww0.x); ffma2(s1, v0.y, ww0.y);
                ffma2(s0, v1.x, ww1.x); ffma2(s1, v1.y, ww1.y);
                ffma2(s0, v2.x, ww2.x); ffma2(s1, v2.y, ww2.y);
                ffma2(s0, v3.x, ww3.x); ffma2(s1, v3.y, ww3.y);
                accS[(wbase + p) * 33 + lane] += hsum2(s0) + hsum2(s1);
            }
        }
    }

    int pbase = pidx - lane;
    float sc = g_sc2[lane], shv = g_sh2[lane];
#pragma unroll 4
    for (int p = 0; p < 32; p++) {
        float a = accS[(wbase + p) * 33 + lane];
        unsigned mp = __shfl_sync(0xffffffffu, mask, p);
        float m = mp ? 1.f : 0.f;
        g_h2[(size_t)(pbase + p) * 32 + lane] = fmaxf(fmaf(a, sc, shv), 0.f) * m;
    }
    g_m2[pbase + lane] = (mask != 0) ? 1 : 0;
}

// ---------------- conv3 (R15): 64-pt tile, 3-stage cp.async, f32x2, m3 fused ----------------
__global__ void __launch_bounds__(256, 3) k_conv3() {
    extern __shared__ __align__(16) float dynS[];
    float* As  = dynS;
    float* Wst = dynS + 3 * 2048;
    __shared__ float mS[64];

    int bx = blockIdx.x;
    int ow0 = (bx & 3) * 16;
    int oh0 = ((bx >> 2) & 15) * 4;
    int odb = bx >> 6;
    int od = odb % D3, b = odb / D3;

    int tid = threadIdx.x;
    int cog = tid & 15;  int co4 = cog * 4;
    int p4 = (tid >> 4) * 4;

    unsigned long long acc2[16];
#pragma unroll
    for (int i = 0; i < 16; i++) acc2[i] = 0ull;

    const float4* h2f4  = reinterpret_cast<const float4*>(g_h2);
    const float4* wt3p4 = reinterpret_cast<const float4*>(g_wt3p);
    uint32_t asAddr = smem_u32(As);
    uint32_t wsAddr = smem_u32(Wst);

    int pA0 = tid >> 3, fA = tid & 7;
    int pA1 = (tid + 256) >> 3;
    int diA0 = pA0 >> 4, djA0 = pA0 & 15;
    int diA1 = pA1 >> 4, djA1 = pA1 & 15;

    auto stage = [&](int slot, int tap) {
        int kd = tap / 9; int r9 = tap - 9 * kd; int kh = r9 / 3; int kw = r9 - 3 * kh;
        int id = 2 * od + kd;
        size_t plane = (((size_t)b * D2 + id) * H2) * W2;
        {
            int ih = 2 * (oh0 + diA0) - 1 + kh, iw = 2 * (ow0 + djA0) - 1 + kw;
            bool ok = ((unsigned)ih < (unsigned)H2) && ((unsigned)iw < (unsigned)W2);
            const float4* src = ok ? &h2f4[(plane + (size_t)ih * W2 + iw) * 8 + fA] : h2f4;
            CP_A16(asAddr + (unsigned)(slot * 512 + tid) * 16, src, ok ? 16 : 0);
        }
        {
            int ih = 2 * (oh0 + diA1) - 1 + kh, iw = 2 * (ow0 + djA1) - 1 + kw;
            bool ok = ((unsigned)ih < (unsigned)H2) && ((unsigned)iw < (unsigned)W2);
            const float4* src = ok ? &h2f4[(plane + (size_t)ih * W2 + iw) * 8 + fA] : h2f4;
            CP_A16(asAddr + (unsigned)(slot * 512 + tid + 256) * 16, src, ok ? 16 : 0);
        }
        CP_A16(wsAddr + (unsigned)(slot * 512 + tid) * 16,       &wt3p4[tap * 512 + tid],       16);
        CP_A16(wsAddr + (unsigned)(slot * 512 + tid + 256) * 16, &wt3p4[tap * 512 + tid + 256], 16);
        CP_COMMIT();
    };

    if (tid < 64) {
        int di = tid >> 4, dj = tid & 15;
        int ohp = oh0 + di, owp = ow0 + dj;
        unsigned char m = 0;
#pragma unroll
        for (int kd = 0; kd < 3; kd++) {
            int id = 2 * od + kd;
#pragma unroll
            for (int kh = 0; kh < 3; kh++) {
                int ih = 2 * ohp - 1 + kh;
                if ((unsigned)ih >= (unsigned)H2) continue;
#pragma unroll
                for (int kw = 0; kw < 3; kw++) {
                    int iw = 2 * owp - 1 + kw;
                    if ((unsigned)iw >= (unsigned)W2) continue;
                    size_t cin = (((size_t)b * D2 + id) * H2 + ih) * W2 + iw;
                    m |= g_m2[cin];
                }
            }
        }
        unsigned char mv = m ? 1 : 0;
        mS[tid] = (float)mv;
        g_m3[((b * D3 + od) * H3 + ohp) * W3 + owp] = mv;
    }

    stage(0, 0);
    stage(1, 1);

    int slotc = 0;
#pragma unroll 1
    for (int tap = 0; tap < 27; tap++) {
        if (tap < 26) CP_WAIT1(); else CP_WAIT0();
        __syncthreads();

        const float* Asb = As + slotc * 2048;
        const float* Wsb = Wst + slotc * 2048;
#pragma unroll
        for (int c4 = 0; c4 < 8; c4++) {
            ulonglong2 wa01 = *reinterpret_cast<const ulonglong2*>(&Wsb[(2*c4) * 128 + cog * 4]);
            ulonglong2 wa23 = *reinterpret_cast<const ulonglong2*>(&Wsb[(2*c4) * 128 + 64 + cog * 4]);
            ulonglong2 wb01 = *reinterpret_cast<const ulonglong2*>(&Wsb[(2*c4+1) * 128 + cog * 4]);
            ulonglong2 wb23 = *reinterpret_cast<const ulonglong2*>(&Wsb[(2*c4+1) * 128 + 64 + cog * 4]);
            ulonglong2 A0 = *reinterpret_cast<const ulonglong2*>(&Asb[(p4 + 0) * 32 + 4 * c4]);
            ulonglong2 A1 = *reinterpret_cast<const ulonglong2*>(&Asb[(p4 + 1) * 32 + 4 * c4]);
            ulonglong2 A2 = *reinterpret_cast<const ulonglong2*>(&Asb[(p4 + 2) * 32 + 4 * c4]);
            ulonglong2 A3 = *reinterpret_cast<const ulonglong2*>(&Asb[(p4 + 3) * 32 + 4 * c4]);
            ffma2(acc2[0],  A0.x, wa01.x); ffma2(acc2[1],  A0.x, wa01.y);
            ffma2(acc2[2],  A0.x, wa23.x); ffma2(acc2[3],  A0.x, wa23.y);
            ffma2(acc2[0],  A0.y, wb01.x); ffma2(acc2[1],  A0.y, wb01.y);
            ffma2(acc2[2],  A0.y, wb23.x); ffma2(acc2[3],  A0.y, wb23.y);
            ffma2(acc2[4],  A1.x, wa01.x); ffma2(acc2[5],  A1.x, wa01.y);
            ffma2(acc2[6],  A1.x, wa23.x); ffma2(acc2[7],  A1.x, wa23.y);
            ffma2(acc2[4],  A1.y, wb01.x); ffma2(acc2[5],  A1.y, wb01.y);
            ffma2(acc2[6],  A1.y, wb23.x); ffma2(acc2[7],  A1.y, wb23.y);
            ffma2(acc2[8],  A2.x, wa01.x); ffma2(acc2[9],  A2.x, wa01.y);
            ffma2(acc2[10], A2.x, wa23.x); ffma2(acc2[11], A2.x, wa23.y);
            ffma2(acc2[8],  A2.y, wb01.x); ffma2(acc2[9],  A2.y, wb01.y);
            ffma2(acc2[10], A2.y, wb23.x); ffma2(acc2[11], A2.y, wb23.y);
            ffma2(acc2[12], A3.x, wa01.x); ffma2(acc2[13], A3.x, wa01.y);
            ffma2(acc2[14], A3.x, wa23.x); ffma2(acc2[15], A3.x, wa23.y);
            ffma2(acc2[12], A3.y, wb01.x); ffma2(acc2[13], A3.y, wb01.y);
            ffma2(acc2[14], A3.y, wb23.x); ffma2(acc2[15], A3.y, wb23.y);
        }

        if (tap + 2 < 27) {
            int slotn = slotc + 2; if (slotn >= 3) slotn -= 3;
            stage(slotn, tap + 2);
        }
        if (++slotc == 3) slotc = 0;
    }

    float sc[4], sh[4];
#pragma unroll
    for (int j = 0; j < 4; j++) { sc[j] = g_sc3[co4 + j]; sh[j] = g_sh3[co4 + j]; }
#pragma unroll
    for (int e = 0; e < 4; e++) {
        int p = p4 + e;
        int di = p >> 4, dj = p & 15;
        int lin = ((b * D3 + od) * H3 + (oh0 + di)) * W3 + (ow0 + dj);
        float m = mS[p];
        float4 o;
        o.x = fmaxf(fmaf(hsum2(acc2[e*4+0]), sc[0], sh[0]), 0.f) * m;
        o.y = fmaxf(fmaf(hsum2(acc2[e*4+1]), sc[1], sh[1]), 0.f) * m;
        o.z = fmaxf(fmaf(hsum2(acc2[e*4+2]), sc[2], sh[2]), 0.f) * m;
        o.w = fmaxf(fmaf(hsum2(acc2[e*4+3]), sc[3], sh[3]), 0.f) * m;
        *reinterpret_cast<float4*>(&g_h3[(size_t)lin * 64 + co4]) = o;
    }
}

// ---------------- conv4 + fused clean ----------------
__global__ void __launch_bounds__(256) k_conv4(float* __restrict__ out,
                                               const int* __restrict__ coors, int nv) {
    if (blockIdx.x >= CONV4_BLOCKS) {
        int i = (blockIdx.x - CONV4_BLOCKS) * 256 + threadIdx.x;
        if (i < nv) {
            int b = coors[4*i], z = coors[4*i+1], y = coors[4*i+2], x = coors[4*i+3];
            size_t cell = (((size_t)b * D0 + z) * H0 + y) * W0 + x;
            g_dense0[cell] = make_float4(0.f, 0.f, 0.f, 0.f);
            g_bits[cell >> 5] = 0u;
        }
        return;
    }

    int gw = (blockIdx.x * blockDim.x + threadIdx.x) >> 5;
    int lane = threadIdx.x & 31;
    int ow = gw & 63; int t = gw >> 6;
    int oh = t & 63; t >>= 6;
    int od = t & 1; int b = t >> 1;

    unsigned on = 0;
    if (lane < 3) {
        int id = 2*od + lane;
        size_t cin = (((size_t)b * D3 + id) * H3 + oh) * W3 + ow;
        on = g_m3[cin];
    }
    unsigned bits = __ballot_sync(0xffffffffu, on != 0);

    size_t obase = (size_t)b * 128 * 4096 + (size_t)oh * 64 + ow;
    size_t oi0 = obase + (size_t)(lane * 2 + od) * 4096;
    size_t oi1 = obase + (size_t)((lane + 32) * 2 + od) * 4096;

    if (!bits) { out[oi0] = 0.f; out[oi1] = 0.f; return; }

    unsigned long long acc0 = 0ull, acc1 = 0ull;
    const ulonglong2* wtb = reinterpret_cast<const ulonglong2*>(g_wt4);
#pragma unroll
    for (int kd = 0; kd < 3; kd++) {
        if (bits & (1u << kd)) {
            int id = 2*od + kd;
            size_t cin = (((size_t)b * D3 + id) * H3 + oh) * W3 + ow;
            const ulonglong2* hin = reinterpret_cast<const ulonglong2*>(&g_h3[cin * 64]);
            const ulonglong2* wv = wtb + kd * 1024 + lane;
#pragma unroll
            for (int gg = 0; gg < 16; gg++) {
                ulonglong2 v  = __ldg(hin + gg);
                ulonglong2 w0 = __ldg(wv + gg * 64);
                ulonglong2 w1 = __ldg(wv + gg * 64 + 32);
                ffma2(acc0, v.x, w0.x); ffma2(acc0, v.y, w0.y);
                ffma2(acc1, v.x, w1.x); ffma2(acc1, v.y, w1.y);
            }
        }
    }
    out[oi0] = fmaxf(fmaf(hsum2(acc0), g_sc4[lane],      g_sh4[lane]),      0.f);
    out[oi1] = fmaxf(fmaf(hsum2(acc1), g_sc4[lane + 32], g_sh4[lane + 32]), 0.f);
}

// ---------------- launch ----------------
extern "C" void kernel_launch(void* const* d_in, const int* in_sizes, int n_in,
                              void* d_out, int out_size) {
    const float* vf    = (const float*)d_in[0];
    const int*   coors = (const int*)d_in[1];
    int nv = in_sizes[0] / 3;

    const float* w1 = (const float*)d_in[3];  const float* g1 = (const float*)d_in[4];
    const float* b1 = (const float*)d_in[5];  const float* m1 = (const float*)d_in[6];
    const float* v1 = (const float*)d_in[7];
    const float* w2 = (const float*)d_in[8];  const float* g2 = (const float*)d_in[9];
    const float* b2 = (const float*)d_in[10]; const float* m2 = (const float*)d_in[11];
    const float* v2 = (const float*)d_in[12];
    const float* w3 = (const float*)d_in[13]; const float* g3 = (const float*)d_in[14];
    const float* b3 = (const float*)d_in[15]; const float* m3 = (const float*)d_in[16];
    const float* v3 = (const float*)d_in[17];
    const float* w4 = (const float*)d_in[18]; const float* g4 = (const float*)d_in[19];
    const float* b4 = (const float*)d_in[20]; const float* m4 = (const float*)d_in[21];
    const float* v4 = (const float*)d_in[22];

    cudaFuncSetAttribute(k_conv3, cudaFuncAttributeMaxDynamicSharedMemorySize, CONV3_SMEM);

    int scat_blocks = (nv + 255) / 256;
    k_prep<<<216, 256>>>(w1, g1, b1, m1, v1,
                         w2, g2, b2, m2, v2,
                         w3, g3, b3, m3, v3,
                         w4, g4, b4, m4, v4);
    k_scat<<<scat_blocks, 256>>>(vf, coors, nv);
    k_mask1<<<N1 / 256, 128>>>();
    k_conv1b<<<2048, 256>>>();
    k_conv2<<<N2 / 256, 256>>>();
    k_conv3<<<640, 256, CONV3_SMEM>>>();
    k_conv4<<<CONV4_BLOCKS + scat_blocks, 256>>>((float*)d_out, coors, nv);
}